// round 12
// baseline (speedup 1.0000x reference)
#include <cuda_runtime.h>

#define BB    64
#define TT    512
#define DD    256
#define WW    50
#define NDIAG (2*TT - 1)     // 1023
#define NDPAD 1040           // padded so prefetch never goes OOB
#define BIGF  1e9f

#define TI 16
#define TJ 128
#define KC 32

// scratch (no allocations allowed -> __device__ globals)
__device__ float g_costD[(size_t)BB * NDPAD * 64];   // ~17 MB, L2-resident
__device__ float g_rn1[BB * TT];
__device__ float g_rn2[BB * TT];

__global__ void noop_kernel() {}

// packed fp32 helpers
#define FMA_F32X2(acc, a, b) \
    asm("fma.rn.f32x2 %0, %1, %2, %0;" : "+l"(acc) : "l"(a), "l"(b))
#define DUP_F32X2(d, s) \
    asm("mov.b64 %0, {%1, %1};" : "=l"(d) : "f"(s))
#define UNPACK_F32X2(lo, hi, s) \
    asm("mov.b64 {%0, %1}, %2;" : "=f"(lo), "=f"(hi) : "l"(s))

// ---------------------------------------------------------------------------
// Kernel 0: fill cost array with BIG (out-of-band cells self-poison the DP)
// ---------------------------------------------------------------------------
__global__ void fill_kernel() {
    size_t n = (size_t)BB * NDPAD * 64 / 4;
    size_t idx = (size_t)blockIdx.x * blockDim.x + threadIdx.x;
    if (idx < n)
        ((float4*)g_costD)[idx] = make_float4(BIGF, BIGF, BIGF, BIGF);
}

// ---------------------------------------------------------------------------
// Kernel 1: reciprocal norms  rn = 1 / max(||x||, eps)
// ---------------------------------------------------------------------------
__global__ void norm_kernel(const float* __restrict__ x1,
                            const float* __restrict__ x2) {
    int warp = (blockIdx.x * blockDim.x + threadIdx.x) >> 5;
    int lane = threadIdx.x & 31;
    if (warp >= 2 * BB * TT) return;
    const float* src;
    float* dst;
    if (warp < BB * TT) { src = x1 + (size_t)warp * DD;            dst = g_rn1 + warp; }
    else                { src = x2 + (size_t)(warp - BB*TT) * DD;  dst = g_rn2 + (warp - BB*TT); }
    const float4* p4 = (const float4*)src;
    float4 a = p4[lane];
    float4 c = p4[lane + 32];
    float s = a.x*a.x + a.y*a.y + a.z*a.z + a.w*a.w
            + c.x*c.x + c.y*c.y + c.z*c.z + c.w*c.w;
    #pragma unroll
    for (int o = 16; o > 0; o >>= 1) s += __shfl_xor_sync(0xffffffffu, s, o);
    if (lane == 0) *dst = 1.0f / fmaxf(sqrtf(s), 1e-8f);
}

// ---------------------------------------------------------------------------
// Kernel 2: banded cost (R6 structure: 128 threads, 4x4 tile, XOR-swizzled
// smem, staged coalesced diagonal stores) with j-pair FFMA2 inner loop:
// B pairs come pre-packed from ulonglong2 LDS (no pack MOVs), A dup'd 4x/k.
//   g_costD[b][d][i & 63] = 1 - <x1_i, x2_j> * rn1_i * rn2_j,   d = i + j
// ---------------------------------------------------------------------------
__global__ void cost_kernel(const float* __restrict__ x1,
                            const float* __restrict__ x2) {
    __shared__ float As[KC][TI];
    __shared__ float Bs[KC][TJ];
    __shared__ float rn1s[TI];
    __shared__ float rn2s[TJ];

    int b   = blockIdx.y;
    int i0  = blockIdx.x * TI;
    int j0  = i0 - 56;
    int tid = threadIdx.x;              // 128 threads
    int lane = tid & 31;
    int w    = tid >> 5;

    const float* X1 = x1 + (size_t)b * TT * DD;
    const float* X2 = x2 + (size_t)b * TT * DD;

    if (tid < TI) rn1s[tid] = g_rn1[b * TT + i0 + tid];
    {
        int j  = j0 + tid;
        int jc = min(max(j, 0), TT - 1);
        rn2s[tid] = g_rn2[b * TT + jc];
    }

    int r  = tid >> 3;                  // 0..15: row-within-pass
    int cg = tid & 7;                   // k granule (16B chunk)

    unsigned long long acc2[4][2];      // [ii][j-pair], each = {f32,f32}
    #pragma unroll
    for (int ii = 0; ii < 4; ii++) { acc2[ii][0] = 0ull; acc2[ii][1] = 0ull; }

    for (int kc = 0; kc < DD; kc += KC) {
        __syncthreads();
        {   // A tile: 16 rows x 32 cols, coalesced, swizzled STS
            float4 v = *(const float4*)(X1 + (size_t)(i0 + r) * DD + kc + cg * 4);
            int gi = r >> 2, il = r & 3;
            int pi = (((gi ^ (cg & 3)) << 2) | il);
            As[cg*4+0][pi] = v.x;
            As[cg*4+1][pi] = v.y;
            As[cg*4+2][pi] = v.z;
            As[cg*4+3][pi] = v.w;
        }
        #pragma unroll
        for (int p = 0; p < 8; p++) {   // B tile: 128 rows x 32 cols
            int j  = p * 16 + r;
            int jr = min(max(j0 + j, 0), TT - 1);
            float4 v = *(const float4*)(X2 + (size_t)jr * DD + kc + cg * 4);
            int gj = j >> 2, jl = j & 3;
            int pj = (((gj ^ cg) << 2) | jl);
            Bs[cg*4+0][pj] = v.x;
            Bs[cg*4+1][pj] = v.y;
            Bs[cg*4+2][pj] = v.z;
            Bs[cg*4+3][pj] = v.w;
        }
        __syncthreads();
        #pragma unroll
        for (int k = 0; k < KC; k++) {
            int sA = (k >> 2) & 3;
            int sB = (k >> 2) & 7;
            float4 a4 = *(const float4*)&As[k][(w    ^ sA) << 2];
            ulonglong2 bp = *(const ulonglong2*)&Bs[k][(lane ^ sB) << 2];
            unsigned long long ad0, ad1, ad2, ad3;
            DUP_F32X2(ad0, a4.x);
            DUP_F32X2(ad1, a4.y);
            DUP_F32X2(ad2, a4.z);
            DUP_F32X2(ad3, a4.w);
            FMA_F32X2(acc2[0][0], ad0, bp.x); FMA_F32X2(acc2[0][1], ad0, bp.y);
            FMA_F32X2(acc2[1][0], ad1, bp.x); FMA_F32X2(acc2[1][1], ad1, bp.y);
            FMA_F32X2(acc2[2][0], ad2, bp.x); FMA_F32X2(acc2[2][1], ad2, bp.y);
            FMA_F32X2(acc2[3][0], ad3, bp.x); FMA_F32X2(acc2[3][1], ad3, bp.y);
        }
    }

    // stage results in smem (aliases Bs: 16x128 floats)
    __syncthreads();
    float (*stage)[TJ] = (float (*)[TJ])&Bs[0][0];
    #pragma unroll
    for (int ii = 0; ii < 4; ii++) {
        float j0v, j1v, j2v, j3v;
        UNPACK_F32X2(j0v, j1v, acc2[ii][0]);
        UNPACK_F32X2(j2v, j3v, acc2[ii][1]);
        *(float4*)&stage[w*4 + ii][lane*4] = make_float4(j0v, j1v, j2v, j3v);
    }
    __syncthreads();

    // coalesced diagonal-major store: warp handles one diagonal at a time
    int dlo = i0 + j0;
    for (int dd = w; dd < TI + TJ - 1; dd += 4) {
        int d = dlo + dd;
        if (d < 0 || d >= NDIAG) continue;
        int ilo_d  = max(0, max(d - (TT-1), (d - (WW-1)) >> 1));
        int ihi_d  = min(TT-1, min(d, (d + WW) >> 1));
        int istart = max(i0, max(ilo_d, d - (j0 + TJ - 1)));
        int iend   = min(i0 + TI - 1, min(ihi_d, d - j0));
        int i = istart + lane;
        if (lane <= iend - istart) {
            int jj = d - i - j0;
            float v = 1.0f - stage[i - i0][jj] * rn1s[i - i0] * rn2s[jj];
            g_costD[((size_t)b * NDPAD + d) * 64 + (i & 63)] = v;
        }
    }
}

// ---------------------------------------------------------------------------
// Kernel 3: warp-synchronous banded DTW, 2 diagonals/round, adjacent-pair
// layout (lane t = cells 2t, 2t+1), R10-proven 5-shfl step, TWO independent
// batches interleaved per warp to hide the serial-chain latency.
// ---------------------------------------------------------------------------
__global__ void dtw_kernel(float* __restrict__ out) {
    int bb = blockIdx.x;                  // 0..31 -> batches 2bb, 2bb+1
    int t  = threadIdx.x;                 // 32 threads
    const float* cbA = g_costD + (size_t)(2*bb)     * NDPAD * 64;
    const float* cbB = g_costD + (size_t)(2*bb + 1) * NDPAD * 64;
    int sl = (t + 31) & 31;               // neighbor lane (cells -2/-1)

    float2 uA, uB;
#define LOADSLOT(DB, AE0, AO0, AE1, AO1, BE0, BO0, BE1, BO1)                  \
    uA = *(const float2*)(cbA + (size_t)(DB) * 64 + 2*t);                     \
    AE0 = uA.x; AO0 = uA.y;                                                   \
    uA = *(const float2*)(cbA + (size_t)((DB)+1) * 64 + 2*t);                 \
    AE1 = uA.x; AO1 = uA.y;                                                   \
    uB = *(const float2*)(cbB + (size_t)(DB) * 64 + 2*t);                     \
    BE0 = uB.x; BO0 = uB.y;                                                   \
    uB = *(const float2*)(cbB + (size_t)((DB)+1) * 64 + 2*t);                 \
    BE1 = uB.x; BO1 = uB.y;

    // 4 queue slots x (2 diagonals) x 2 batches, explicit scalars
    float a0E0,a0O0,a0E1,a0O1, b0E0,b0O0,b0E1,b0O1;
    float a1E0,a1O0,a1E1,a1O1, b1E0,b1O0,b1E1,b1O1;
    float a2E0,a2O0,a2E1,a2O1, b2E0,b2O0,b2E1,b2O1;
    float a3E0,a3O0,a3E1,a3O1, b3E0,b3O0,b3E1,b3O1;
    LOADSLOT(0, a0E0,a0O0,a0E1,a0O1, b0E0,b0O0,b0E1,b0O1)
    LOADSLOT(2, a1E0,a1O0,a1E1,a1O1, b1E0,b1O0,b1E1,b1O1)
    LOADSLOT(4, a2E0,a2O0,a2E1,a2O1, b2E0,b2O0,b2E1,b2O1)
    LOADSLOT(6, a3E0,a3O0,a3E1,a3O1, b3E0,b3O0,b3E1,b3O1)

    // init diagonals 0,1 explicitly for both batches
    float c00A = __shfl_sync(0xffffffffu, a0E0, 0);    // costA(0,0)
    float c00B = __shfl_sync(0xffffffffu, b0E0, 0);    // costB(0,0)
    float p2EA = (t == 0) ? c00A : BIGF, p2OA = BIGF;
    float p1EA = (t == 0) ? a0E1 + c00A : BIGF;
    float p1OA = (t == 0) ? a0O1 + c00A : BIGF;
    float p2EB = (t == 0) ? c00B : BIGF, p2OB = BIGF;
    float p1EB = (t == 0) ? b0E1 + c00B : BIGF;
    float p1OB = (t == 0) ? b0O1 + c00B : BIGF;
    LOADSLOT(8, a0E0,a0O0,a0E1,a0O1, b0E0,b0O0,b0E1,b0O1)   // slot0 -> D=8,9

#define PSTEP(D, AE0, AO0, AE1, AO1, BE0, BO0, BE1, BO1)                      \
    {                                                                         \
        float CDEA = AE0, CDOA = AO0, CEEA = AE1, CEOA = AO1;                 \
        float CDEB = BE0, CDOB = BO0, CEEB = BE1, CEOB = BO1;                 \
        LOADSLOT((D)+8, AE0,AO0,AE1,AO1, BE0,BO0,BE1,BO1)                     \
        float aA  = __shfl_sync(0xffffffffu, p1OA, sl);                       \
        float bqA = __shfl_sync(0xffffffffu, p1EA, sl);                       \
        float eA  = __shfl_sync(0xffffffffu, p2OA, sl);                       \
        float fA  = __shfl_sync(0xffffffffu, p2EA, sl);                       \
        float kOA = __shfl_sync(0xffffffffu, CDOA, sl);                       \
        float aB  = __shfl_sync(0xffffffffu, p1OB, sl);                       \
        float bqB = __shfl_sync(0xffffffffu, p1EB, sl);                       \
        float eB  = __shfl_sync(0xffffffffu, p2OB, sl);                       \
        float fB  = __shfl_sync(0xffffffffu, p2EB, sl);                       \
        float kOB = __shfl_sync(0xffffffffu, CDOB, sl);                       \
        float AD_EA = CDEA + fminf(fminf(p1EA, aA), eA);                      \
        float AD_OA = CDOA + fminf(fminf(p1OA, p1EA), p2EA);                  \
        float t1EA  = CDEA + fminf(p1EA, eA);                                 \
        float t1OA  = CDOA + fminf(p1OA, p2EA);                               \
        float t3EA  = kOA  + fminf(bqA, fA);                                  \
        float t3OA  = CDEA + fminf(aA, eA);                                   \
        float AE_EA = CEEA + fminf(fminf(t1EA, aA),   t3EA);                  \
        float AE_OA = CEOA + fminf(fminf(t1OA, p1EA), t3OA);                  \
        float AD_EB = CDEB + fminf(fminf(p1EB, aB), eB);                      \
        float AD_OB = CDOB + fminf(fminf(p1OB, p1EB), p2EB);                  \
        float t1EB  = CDEB + fminf(p1EB, eB);                                 \
        float t1OB  = CDOB + fminf(p1OB, p2EB);                               \
        float t3EB  = kOB  + fminf(bqB, fB);                                  \
        float t3OB  = CDEB + fminf(aB, eB);                                   \
        float AE_EB = CEEB + fminf(fminf(t1EB, aB),   t3EB);                  \
        float AE_OB = CEOB + fminf(fminf(t1OB, p1EB), t3OB);                  \
        if ((D) == 1022 && t == 31) {                                         \
            out[2*bb]     = AD_OA;       /* cell 63 = (511,511) */            \
            out[2*bb + 1] = AD_OB;                                            \
        }                                                                     \
        p2EA = AD_EA; p2OA = AD_OA; p1EA = AE_EA; p1OA = AE_OA;               \
        p2EB = AD_EB; p2OB = AD_OB; p1EB = AE_EB; p1OB = AE_OB;               \
    }

    // prologue: D=2,4,6 (slots 1..3), then 127 x 4 rounds: D=8..1022
    PSTEP(2, a1E0,a1O0,a1E1,a1O1, b1E0,b1O0,b1E1,b1O1)
    PSTEP(4, a2E0,a2O0,a2E1,a2O1, b2E0,b2O0,b2E1,b2O1)
    PSTEP(6, a3E0,a3O0,a3E1,a3O1, b3E0,b3O0,b3E1,b3O1)
    for (int dbase = 8; dbase <= 1016; dbase += 8) {
        PSTEP(dbase + 0, a0E0,a0O0,a0E1,a0O1, b0E0,b0O0,b0E1,b0O1)
        PSTEP(dbase + 2, a1E0,a1O0,a1E1,a1O1, b1E0,b1O0,b1E1,b1O1)
        PSTEP(dbase + 4, a2E0,a2O0,a2E1,a2O1, b2E0,b2O0,b2E1,b2O1)
        PSTEP(dbase + 6, a3E0,a3O0,a3E1,a3O1, b3E0,b3O0,b3E1,b3O1)
    }
#undef PSTEP
#undef LOADSLOT
}

// ---------------------------------------------------------------------------
extern "C" void kernel_launch(void* const* d_in, const int* in_sizes, int n_in,
                              void* d_out, int out_size) {
    const float* x1 = (const float*)d_in[0];
    const float* x2 = (const float*)d_in[1];
    float* out = (float*)d_out;

    noop_kernel<<<1, 32>>>();                           // slot 0
    fill_kernel<<<4160, 256>>>();                       // slot 1
    norm_kernel<<<(2 * BB * TT) / 8, 256>>>(x1, x2);    // slot 2
    dim3 g(TT / TI, BB);
    cost_kernel<<<g, 128>>>(x1, x2);                    // slot 3 (profiled)
    dtw_kernel<<<BB/2, 32>>>(out);                      // slot 4
}

// round 14
// speedup vs baseline: 1.4917x; 1.4917x over previous
#include <cuda_runtime.h>
#include <cuda_bf16.h>

#define BB    64
#define TT    512
#define DD    256
#define WW    50
#define NDIAG (2*TT - 1)     // 1023
#define NDPAD 1040           // padded so 16-deep prefetch never goes OOB
#define BIGF  1e9f

#define TI 16
#define TJ 128

// scratch (no allocations allowed -> __device__ globals)
__device__ float g_costD[(size_t)BB * NDPAD * 64];   // ~17 MB, L2-resident
__device__ float g_rn1[BB * TT];
__device__ float g_rn2[BB * TT];

__global__ void noop_kernel() {}

// pack two fp32 -> bf16x2 (lo in low half)
__device__ __forceinline__ unsigned cvt2(float lo, float hi) {
    unsigned r;
    asm("cvt.rn.bf16x2.f32 %0, %1, %2;" : "=r"(r) : "f"(hi), "f"(lo));
    return r;
}

#define MMA_BF16(c0,c1,c2,c3, a0,a1,a2,a3, b0,b1)                       \
    asm volatile("mma.sync.aligned.m16n8k16.row.col.f32.bf16.bf16.f32 " \
        "{%0,%1,%2,%3}, {%4,%5,%6,%7}, {%8,%9}, {%0,%1,%2,%3};"         \
        : "+f"(c0), "+f"(c1), "+f"(c2), "+f"(c3)                        \
        : "r"(a0), "r"(a1), "r"(a2), "r"(a3), "r"(b0), "r"(b1))

// ---------------------------------------------------------------------------
// Kernel 0: fill cost array with BIG (out-of-band cells self-poison the DP)
// ---------------------------------------------------------------------------
__global__ void fill_kernel() {
    size_t n = (size_t)BB * NDPAD * 64 / 4;
    size_t idx = (size_t)blockIdx.x * blockDim.x + threadIdx.x;
    if (idx < n)
        ((float4*)g_costD)[idx] = make_float4(BIGF, BIGF, BIGF, BIGF);
}

// ---------------------------------------------------------------------------
// Kernel 1: reciprocal norms  rn = 1 / max(||x||, eps)   (fp32, exact)
// ---------------------------------------------------------------------------
__global__ void norm_kernel(const float* __restrict__ x1,
                            const float* __restrict__ x2) {
    int warp = (blockIdx.x * blockDim.x + threadIdx.x) >> 5;
    int lane = threadIdx.x & 31;
    if (warp >= 2 * BB * TT) return;
    const float* src;
    float* dst;
    if (warp < BB * TT) { src = x1 + (size_t)warp * DD;            dst = g_rn1 + warp; }
    else                { src = x2 + (size_t)(warp - BB*TT) * DD;  dst = g_rn2 + (warp - BB*TT); }
    const float4* p4 = (const float4*)src;
    float4 a = p4[lane];
    float4 c = p4[lane + 32];
    float s = a.x*a.x + a.y*a.y + a.z*a.z + a.w*a.w
            + c.x*c.x + c.y*c.y + c.z*c.z + c.w*c.w;
    #pragma unroll
    for (int o = 16; o > 0; o >>= 1) s += __shfl_xor_sync(0xffffffffu, s, o);
    if (lane == 0) *dst = 1.0f / fmaxf(sqrtf(s), 1e-8f);
}

// ---------------------------------------------------------------------------
// Kernel 2: banded cost via bf16 tensor cores (mma.sync m16n8k16, fp32 acc).
//   g_costD[b][d][i & 63] = 1 - <x1_i, x2_j> * rn1_i * rn2_j,   d = i + j
// 128 threads / 4 warps; warp w covers j window [w*32, w*32+32).
// Tiles converted fp32->bf16 into padded smem (72 bf16/row: conflict-free
// LDS.32 fragment loads); diagonal-major store staged as in R6.
// ---------------------------------------------------------------------------
__global__ void cost_kernel(const float* __restrict__ x1,
                            const float* __restrict__ x2) {
    __shared__ __nv_bfloat16 Asb[16][72];    // 2.3 KB
    __shared__ __nv_bfloat16 Bsb[128][72];   // 18.4 KB
    __shared__ float stage[16][132];         // 8.4 KB
    __shared__ float rn1s[TI];
    __shared__ float rn2s[TJ];

    int b    = blockIdx.y;
    int i0   = blockIdx.x * TI;
    int j0   = i0 - 56;                 // window [i0-56, i0+71] superset of band
    int tid  = threadIdx.x;             // 128 threads
    int lane = tid & 31;
    int w    = tid >> 5;
    int g    = lane >> 2;               // fragment group 0..7
    int tig  = lane & 3;                // thread-in-group

    const float* X1 = x1 + (size_t)b * TT * DD;
    const float* X2 = x2 + (size_t)b * TT * DD;

    if (tid < TI) rn1s[tid] = g_rn1[b * TT + i0 + tid];
    {
        int j  = j0 + tid;
        int jc = min(max(j, 0), TT - 1);
        rn2s[tid] = g_rn2[b * TT + jc];
    }

    int r  = tid >> 3;                  // 0..15: row-within-pass
    int cg = tid & 7;                   // 8-float column group

    float c[4][4];                      // [n-tile][frag reg]
    #pragma unroll
    for (int nt = 0; nt < 4; nt++)
        #pragma unroll
        for (int q = 0; q < 4; q++) c[nt][q] = 0.0f;

    for (int kc = 0; kc < DD; kc += 64) {
        __syncthreads();
        {   // A tile: 16 rows x 64 cols -> bf16, one STS.128 per thread
            const float* src = X1 + (size_t)(i0 + r) * DD + kc + cg * 8;
            float4 v0 = *(const float4*)src;
            float4 v1 = *(const float4*)(src + 4);
            uint4 pk = make_uint4(cvt2(v0.x, v0.y), cvt2(v0.z, v0.w),
                                  cvt2(v1.x, v1.y), cvt2(v1.z, v1.w));
            *(uint4*)&Asb[r][cg * 8] = pk;
        }
        #pragma unroll
        for (int p = 0; p < 8; p++) {   // B tile: 128 rows x 64 cols
            int j  = p * 16 + r;
            int jr = min(max(j0 + j, 0), TT - 1);
            const float* src = X2 + (size_t)jr * DD + kc + cg * 8;
            float4 v0 = *(const float4*)src;
            float4 v1 = *(const float4*)(src + 4);
            uint4 pk = make_uint4(cvt2(v0.x, v0.y), cvt2(v0.z, v0.w),
                                  cvt2(v1.x, v1.y), cvt2(v1.z, v1.w));
            *(uint4*)&Bsb[j][cg * 8] = pk;
        }
        __syncthreads();
        #pragma unroll
        for (int k16 = 0; k16 < 4; k16++) {
            int k0 = k16 * 16;
            unsigned a0 = *(const unsigned*)&Asb[g    ][k0 + 2*tig];
            unsigned a1 = *(const unsigned*)&Asb[g + 8][k0 + 2*tig];
            unsigned a2 = *(const unsigned*)&Asb[g    ][k0 + 8 + 2*tig];
            unsigned a3 = *(const unsigned*)&Asb[g + 8][k0 + 8 + 2*tig];
            #pragma unroll
            for (int nt = 0; nt < 4; nt++) {
                int jb = w * 32 + nt * 8;
                unsigned b0 = *(const unsigned*)&Bsb[jb + g][k0 + 2*tig];
                unsigned b1 = *(const unsigned*)&Bsb[jb + g][k0 + 8 + 2*tig];
                MMA_BF16(c[nt][0], c[nt][1], c[nt][2], c[nt][3],
                         a0, a1, a2, a3, b0, b1);
            }
        }
    }

    // fragment -> stage:  c0,c1 = row g, cols 2tig,2tig+1;  c2,c3 = row g+8
    #pragma unroll
    for (int nt = 0; nt < 4; nt++) {
        int jc = w * 32 + nt * 8 + 2 * tig;
        stage[g    ][jc]     = c[nt][0];
        stage[g    ][jc + 1] = c[nt][1];
        stage[g + 8][jc]     = c[nt][2];
        stage[g + 8][jc + 1] = c[nt][3];
    }
    __syncthreads();

    // coalesced diagonal-major store: warp handles one diagonal at a time
    int dlo = i0 + j0;
    for (int dd = w; dd < TI + TJ - 1; dd += 4) {   // 143 diagonals in window
        int d = dlo + dd;
        if (d < 0 || d >= NDIAG) continue;
        int ilo_d  = max(0, max(d - (TT-1), (d - (WW-1)) >> 1));
        int ihi_d  = min(TT-1, min(d, (d + WW) >> 1));
        int istart = max(i0, max(ilo_d, d - (j0 + TJ - 1)));
        int iend   = min(i0 + TI - 1, min(ihi_d, d - j0));
        int i = istart + lane;
        if (lane <= iend - istart) {
            int jj = d - i - j0;
            float v = 1.0f - stage[i - i0][jj] * rn1s[i - i0] * rn2s[jj];
            g_costD[((size_t)b * NDPAD + d) * 64 + (i & 63)] = v;
        }
    }
}

// ---------------------------------------------------------------------------
// Kernel 3: warp-synchronous banded DTW (R10-proven: 54us measured).
// 2 diagonals/round, adjacent-pair layout (lane t = cells 2t, 2t+1), 5 shfl
// per round, zero lane-dependent selects, 16-diagonal register queue.
// ---------------------------------------------------------------------------
__global__ void dtw_kernel(float* __restrict__ out) {
    int b = blockIdx.x;
    int t = threadIdx.x;                  // 32 threads
    const float* cb = g_costD + (size_t)b * NDPAD * 64;
    int sl = (t + 31) & 31;               // neighbor lane (cell index -2/-1)

    float2 u;
#define LOADSLOT(DBASE, E0, O0, E1, O1)                                       \
    u = *(const float2*)(cb + (size_t)(DBASE) * 64 + 2*t); E0 = u.x; O0 = u.y;\
    u = *(const float2*)(cb + (size_t)((DBASE)+1) * 64 + 2*t); E1 = u.x; O1 = u.y;

    float q0E0,q0O0,q0E1,q0O1; LOADSLOT( 0, q0E0,q0O0,q0E1,q0O1)
    float q1E0,q1O0,q1E1,q1O1; LOADSLOT( 2, q1E0,q1O0,q1E1,q1O1)
    float q2E0,q2O0,q2E1,q2O1; LOADSLOT( 4, q2E0,q2O0,q2E1,q2O1)
    float q3E0,q3O0,q3E1,q3O1; LOADSLOT( 6, q3E0,q3O0,q3E1,q3O1)
    float q4E0,q4O0,q4E1,q4O1; LOADSLOT( 8, q4E0,q4O0,q4E1,q4O1)
    float q5E0,q5O0,q5E1,q5O1; LOADSLOT(10, q5E0,q5O0,q5E1,q5O1)
    float q6E0,q6O0,q6E1,q6O1; LOADSLOT(12, q6E0,q6O0,q6E1,q6O1)
    float q7E0,q7O0,q7E1,q7O1; LOADSLOT(14, q7E0,q7O0,q7E1,q7O1)

    // init diagonals 0 and 1 explicitly (origin must not leak through the
    // zero-coefficient term of the pair formula)
    float a00 = __shfl_sync(0xffffffffu, q0E0, 0);     // cost(0,0)
    float p2E = (t == 0) ? a00 : BIGF;                 // A_0: cell 0 only
    float p2O = BIGF;
    float p1E = (t == 0) ? q0E1 + a00 : BIGF;          // A_1: cells 0,1
    float p1O = (t == 0) ? q0O1 + a00 : BIGF;
    LOADSLOT(16, q0E0,q0O0,q0E1,q0O1)                  // slot 0 -> D=16,17

#define PSTEP(D, CE0, CO0, CE1, CO1)                                          \
    {                                                                         \
        float CDE = CE0, CDO = CO0, CEE = CE1, CEO = CO1;                     \
        u = *(const float2*)(cb + (size_t)((D)+16) * 64 + 2*t);               \
        CE0 = u.x; CO0 = u.y;                                                 \
        u = *(const float2*)(cb + (size_t)((D)+17) * 64 + 2*t);               \
        CE1 = u.x; CO1 = u.y;                                                 \
        float a  = __shfl_sync(0xffffffffu, p1O, sl);  /* A1[c-1]E, [c-2]O */ \
        float bq = __shfl_sync(0xffffffffu, p1E, sl);  /* A1[c-2]E */         \
        float e  = __shfl_sync(0xffffffffu, p2O, sl);  /* A2[c-1]E, [c-2]O */ \
        float f  = __shfl_sync(0xffffffffu, p2E, sl);  /* A2[c-2]E */         \
        float kO = __shfl_sync(0xffffffffu, CDO, sl);  /* C_D[c-1]E */        \
        float AD_E = CDE + fminf(fminf(p1E, a), e);                           \
        float AD_O = CDO + fminf(fminf(p1O, p1E), p2E);                       \
        float t1E  = CDE + fminf(p1E, e);                                     \
        float t1O  = CDO + fminf(p1O, p2E);                                   \
        float t3E  = kO  + fminf(bq, f);                                      \
        float t3O  = CDE + fminf(a, e);                                       \
        float AE_E = CEE + fminf(fminf(t1E, a),   t3E);                       \
        float AE_O = CEO + fminf(fminf(t1O, p1E), t3O);                       \
        if ((D) == 1022 && t == 31) out[b] = AD_O;  /* cell 63 = (511,511) */ \
        p2E = AD_E; p2O = AD_O; p1E = AE_E; p1O = AE_O;                       \
    }

    // prologue: D=2..14 (slots 1..7), then 63 x 8 rounds: D=16..1022
    PSTEP( 2, q1E0,q1O0,q1E1,q1O1)
    PSTEP( 4, q2E0,q2O0,q2E1,q2O1)
    PSTEP( 6, q3E0,q3O0,q3E1,q3O1)
    PSTEP( 8, q4E0,q4O0,q4E1,q4O1)
    PSTEP(10, q5E0,q5O0,q5E1,q5O1)
    PSTEP(12, q6E0,q6O0,q6E1,q6O1)
    PSTEP(14, q7E0,q7O0,q7E1,q7O1)
    for (int dbase = 16; dbase <= 1008; dbase += 16) {
        PSTEP(dbase +  0, q0E0,q0O0,q0E1,q0O1)
        PSTEP(dbase +  2, q1E0,q1O0,q1E1,q1O1)
        PSTEP(dbase +  4, q2E0,q2O0,q2E1,q2O1)
        PSTEP(dbase +  6, q3E0,q3O0,q3E1,q3O1)
        PSTEP(dbase +  8, q4E0,q4O0,q4E1,q4O1)
        PSTEP(dbase + 10, q5E0,q5O0,q5E1,q5O1)
        PSTEP(dbase + 12, q6E0,q6O0,q6E1,q6O1)
        PSTEP(dbase + 14, q7E0,q7O0,q7E1,q7O1)
    }
#undef PSTEP
#undef LOADSLOT
}

// ---------------------------------------------------------------------------
extern "C" void kernel_launch(void* const* d_in, const int* in_sizes, int n_in,
                              void* d_out, int out_size) {
    const float* x1 = (const float*)d_in[0];
    const float* x2 = (const float*)d_in[1];
    float* out = (float*)d_out;

    noop_kernel<<<1, 32>>>();                           // slot 0
    fill_kernel<<<4160, 256>>>();                       // slot 1
    norm_kernel<<<(2 * BB * TT) / 8, 256>>>(x1, x2);    // slot 2
    dim3 g(TT / TI, BB);
    cost_kernel<<<g, 128>>>(x1, x2);                    // slot 3 (profiled)
    dtw_kernel<<<BB, 32>>>(out);                        // slot 4
}

// round 17
// speedup vs baseline: 2.2247x; 1.4914x over previous
#include <cuda_runtime.h>
#include <cuda_bf16.h>
#include <cstdint>

#define BB    64
#define TT    512
#define DD    256
#define WW    50
#define NDIAG (2*TT - 1)     // 1023
#define NDPAD 1040           // padded so 16-deep prefetch never goes OOB
#define BIGF  1e9f

#define TI 16
#define TJ 128

// scratch (no allocations allowed -> __device__ globals)
__device__ float g_costD[(size_t)BB * NDPAD * 64];        // ~17 MB
__device__ float g_rn1[BB * TT];
__device__ float g_rn2[BB * TT];
__device__ __nv_bfloat16 g_x1b[(size_t)BB * TT * DD];     // 16.8 MB
__device__ __nv_bfloat16 g_x2b[(size_t)BB * TT * DD];     // 16.8 MB

__global__ void noop_kernel() {}

// pack two fp32 -> bf16x2 (lo in low half)
__device__ __forceinline__ unsigned cvt2(float lo, float hi) {
    unsigned r;
    asm("cvt.rn.bf16x2.f32 %0, %1, %2;" : "=r"(r) : "f"(hi), "f"(lo));
    return r;
}

__device__ __forceinline__ unsigned smem_u32(const void* p) {
    return (unsigned)__cvta_generic_to_shared(p);
}

#define LDSM_X4(r0,r1,r2,r3, addr)                                        \
    asm volatile("ldmatrix.sync.aligned.m8n8.x4.shared.b16 "              \
        "{%0,%1,%2,%3}, [%4];"                                            \
        : "=r"(r0), "=r"(r1), "=r"(r2), "=r"(r3) : "r"(addr))

#define MMA_BF16(c0,c1,c2,c3, a0,a1,a2,a3, b0,b1)                       \
    asm volatile("mma.sync.aligned.m16n8k16.row.col.f32.bf16.bf16.f32 " \
        "{%0,%1,%2,%3}, {%4,%5,%6,%7}, {%8,%9}, {%0,%1,%2,%3};"         \
        : "+f"(c0), "+f"(c1), "+f"(c2), "+f"(c3)                        \
        : "r"(a0), "r"(a1), "r"(a2), "r"(a3), "r"(b0), "r"(b1))

// ---------------------------------------------------------------------------
// Kernel 0: fill cost array with BIG (out-of-band cells self-poison the DP)
// ---------------------------------------------------------------------------
__global__ void fill_kernel() {
    size_t n = (size_t)BB * NDPAD * 64 / 4;
    size_t idx = (size_t)blockIdx.x * blockDim.x + threadIdx.x;
    if (idx < n)
        ((float4*)g_costD)[idx] = make_float4(BIGF, BIGF, BIGF, BIGF);
}

// ---------------------------------------------------------------------------
// Kernel 1: reciprocal norms (fp32, exact) + one-time fp32->bf16 conversion
// of the full inputs (so cost_kernel never converts and loads half the bytes)
// ---------------------------------------------------------------------------
__global__ void norm_kernel(const float* __restrict__ x1,
                            const float* __restrict__ x2) {
    int warp = (blockIdx.x * blockDim.x + threadIdx.x) >> 5;
    int lane = threadIdx.x & 31;
    if (warp >= 2 * BB * TT) return;
    const float* src;
    float* dst;
    __nv_bfloat16* bdst;
    if (warp < BB * TT) {
        src  = x1 + (size_t)warp * DD;
        dst  = g_rn1 + warp;
        bdst = g_x1b + (size_t)warp * DD;
    } else {
        int rw = warp - BB * TT;
        src  = x2 + (size_t)rw * DD;
        dst  = g_rn2 + rw;
        bdst = g_x2b + (size_t)rw * DD;
    }
    const float4* p4 = (const float4*)src;
    float4 a = p4[lane];
    float4 c = p4[lane + 32];
    // bf16 copy (elements 4*lane.. and 128+4*lane..)
    uint2* b2 = (uint2*)bdst;
    b2[lane]      = make_uint2(cvt2(a.x, a.y), cvt2(a.z, a.w));
    b2[lane + 32] = make_uint2(cvt2(c.x, c.y), cvt2(c.z, c.w));
    float s = a.x*a.x + a.y*a.y + a.z*a.z + a.w*a.w
            + c.x*c.x + c.y*c.y + c.z*c.z + c.w*c.w;
    #pragma unroll
    for (int o = 16; o > 0; o >>= 1) s += __shfl_xor_sync(0xffffffffu, s, o);
    if (lane == 0) *dst = 1.0f / fmaxf(sqrtf(s), 1e-8f);
}

// ---------------------------------------------------------------------------
// Kernel 2: banded cost via bf16 tensor cores (mma.sync m16n8k16, fp32 acc).
//   g_costD[b][d][i & 63] = 1 - <x1_i, x2_j> * rn1_i * rn2_j,   d = i + j
// Inputs pre-converted to bf16; fragments via ldmatrix.x4 (3 LDSM per k16
// instead of 12 LDS.32); 72-elem row pad keeps every ldmatrix phase
// conflict-free (row stride 36 banks = 4 mod 32 -> 8 rows hit 32 banks once).
// ---------------------------------------------------------------------------
__global__ void cost_kernel() {
    __shared__ __nv_bfloat16 Asb[16][72];    // 2.3 KB
    __shared__ __nv_bfloat16 Bsb[128][72];   // 18.4 KB
    __shared__ float stage[16][132];         // 8.4 KB
    __shared__ float rn1s[TI];
    __shared__ float rn2s[TJ];

    int b    = blockIdx.y;
    int i0   = blockIdx.x * TI;
    int j0   = i0 - 56;                 // window [i0-56, i0+71] superset of band
    int tid  = threadIdx.x;             // 128 threads
    int lane = tid & 31;
    int w    = tid >> 5;
    int g    = lane >> 2;               // fragment group 0..7
    int tig  = lane & 3;                // thread-in-group

    const __nv_bfloat16* X1 = g_x1b + (size_t)b * TT * DD;
    const __nv_bfloat16* X2 = g_x2b + (size_t)b * TT * DD;

    if (tid < TI) rn1s[tid] = g_rn1[b * TT + i0 + tid];
    {
        int j  = j0 + tid;
        int jc = min(max(j, 0), TT - 1);
        rn2s[tid] = g_rn2[b * TT + jc];
    }

    int r  = tid >> 3;                  // 0..15: row-within-pass
    int cg = tid & 7;                   // 8-elem (16B) column group

    // ldmatrix lane addressing (row/col offsets within a 16x16 A tile and a
    // 16-row B pair-tile)
    int a_row = (lane & 7) + (((lane >> 3) & 1) << 3);
    int a_col = (lane >> 4) << 3;
    int b_row = ((lane >> 4) << 3) + (lane & 7);
    int b_col = ((lane >> 3) & 1) << 3;

    float c[4][4];                      // [n-tile][frag reg]
    #pragma unroll
    for (int nt = 0; nt < 4; nt++)
        #pragma unroll
        for (int q = 0; q < 4; q++) c[nt][q] = 0.0f;

    for (int kc = 0; kc < DD; kc += 64) {
        __syncthreads();
        // A tile: 16 rows x 64 bf16, one 16B copy per thread
        *(uint4*)&Asb[r][cg * 8] =
            *(const uint4*)(X1 + (size_t)(i0 + r) * DD + kc + cg * 8);
        #pragma unroll
        for (int p = 0; p < 8; p++) {   // B tile: 128 rows x 64 bf16
            int j  = p * 16 + r;
            int jr = min(max(j0 + j, 0), TT - 1);
            *(uint4*)&Bsb[j][cg * 8] =
                *(const uint4*)(X2 + (size_t)jr * DD + kc + cg * 8);
        }
        __syncthreads();
        #pragma unroll
        for (int k16 = 0; k16 < 4; k16++) {
            int k0 = k16 * 16;
            unsigned a0, a1, a2, a3;
            LDSM_X4(a0, a1, a2, a3, smem_u32(&Asb[a_row][k0 + a_col]));
            #pragma unroll
            for (int pr = 0; pr < 2; pr++) {
                int jb = w * 32 + pr * 16;
                unsigned b0, b1, b2, b3;
                LDSM_X4(b0, b1, b2, b3,
                        smem_u32(&Bsb[jb + b_row][k0 + b_col]));
                MMA_BF16(c[2*pr][0], c[2*pr][1], c[2*pr][2], c[2*pr][3],
                         a0, a1, a2, a3, b0, b1);
                MMA_BF16(c[2*pr+1][0], c[2*pr+1][1], c[2*pr+1][2], c[2*pr+1][3],
                         a0, a1, a2, a3, b2, b3);
            }
        }
    }

    // fragment -> stage:  c0,c1 = row g, cols 2tig,2tig+1;  c2,c3 = row g+8
    #pragma unroll
    for (int nt = 0; nt < 4; nt++) {
        int jc = w * 32 + nt * 8 + 2 * tig;
        stage[g    ][jc]     = c[nt][0];
        stage[g    ][jc + 1] = c[nt][1];
        stage[g + 8][jc]     = c[nt][2];
        stage[g + 8][jc + 1] = c[nt][3];
    }
    __syncthreads();

    // coalesced diagonal-major store: warp handles one diagonal at a time
    int dlo = i0 + j0;
    for (int dd = w; dd < TI + TJ - 1; dd += 4) {   // 143 diagonals in window
        int d = dlo + dd;
        if (d < 0 || d >= NDIAG) continue;
        int ilo_d  = max(0, max(d - (TT-1), (d - (WW-1)) >> 1));
        int ihi_d  = min(TT-1, min(d, (d + WW) >> 1));
        int istart = max(i0, max(ilo_d, d - (j0 + TJ - 1)));
        int iend   = min(i0 + TI - 1, min(ihi_d, d - j0));
        int i = istart + lane;
        if (lane <= iend - istart) {
            int jj = d - i - j0;
            float v = 1.0f - stage[i - i0][jj] * rn1s[i - i0] * rn2s[jj];
            g_costD[((size_t)b * NDPAD + d) * 64 + (i & 63)] = v;
        }
    }
}

// ---------------------------------------------------------------------------
// Kernel 3: warp-synchronous banded DTW (R10-proven: 54us measured).
// 2 diagonals/round, adjacent-pair layout (lane t = cells 2t, 2t+1), 5 shfl
// per round, zero lane-dependent selects, 16-diagonal register queue.
// ---------------------------------------------------------------------------
__global__ void dtw_kernel(float* __restrict__ out) {
    int b = blockIdx.x;
    int t = threadIdx.x;                  // 32 threads
    const float* cb = g_costD + (size_t)b * NDPAD * 64;
    int sl = (t + 31) & 31;               // neighbor lane (cell index -2/-1)

    float2 u;
#define LOADSLOT(DBASE, E0, O0, E1, O1)                                       \
    u = *(const float2*)(cb + (size_t)(DBASE) * 64 + 2*t); E0 = u.x; O0 = u.y;\
    u = *(const float2*)(cb + (size_t)((DBASE)+1) * 64 + 2*t); E1 = u.x; O1 = u.y;

    float q0E0,q0O0,q0E1,q0O1; LOADSLOT( 0, q0E0,q0O0,q0E1,q0O1)
    float q1E0,q1O0,q1E1,q1O1; LOADSLOT( 2, q1E0,q1O0,q1E1,q1O1)
    float q2E0,q2O0,q2E1,q2O1; LOADSLOT( 4, q2E0,q2O0,q2E1,q2O1)
    float q3E0,q3O0,q3E1,q3O1; LOADSLOT( 6, q3E0,q3O0,q3E1,q3O1)
    float q4E0,q4O0,q4E1,q4O1; LOADSLOT( 8, q4E0,q4O0,q4E1,q4O1)
    float q5E0,q5O0,q5E1,q5O1; LOADSLOT(10, q5E0,q5O0,q5E1,q5O1)
    float q6E0,q6O0,q6E1,q6O1; LOADSLOT(12, q6E0,q6O0,q6E1,q6O1)
    float q7E0,q7O0,q7E1,q7O1; LOADSLOT(14, q7E0,q7O0,q7E1,q7O1)

    // init diagonals 0 and 1 explicitly (origin must not leak through the
    // zero-coefficient term of the pair formula)
    float a00 = __shfl_sync(0xffffffffu, q0E0, 0);     // cost(0,0)
    float p2E = (t == 0) ? a00 : BIGF;                 // A_0: cell 0 only
    float p2O = BIGF;
    float p1E = (t == 0) ? q0E1 + a00 : BIGF;          // A_1: cells 0,1
    float p1O = (t == 0) ? q0O1 + a00 : BIGF;
    LOADSLOT(16, q0E0,q0O0,q0E1,q0O1)                  // slot 0 -> D=16,17

#define PSTEP(D, CE0, CO0, CE1, CO1)                                          \
    {                                                                         \
        float CDE = CE0, CDO = CO0, CEE = CE1, CEO = CO1;                     \
        u = *(const float2*)(cb + (size_t)((D)+16) * 64 + 2*t);               \
        CE0 = u.x; CO0 = u.y;                                                 \
        u = *(const float2*)(cb + (size_t)((D)+17) * 64 + 2*t);               \
        CE1 = u.x; CO1 = u.y;                                                 \
        float a  = __shfl_sync(0xffffffffu, p1O, sl);  /* A1[c-1]E, [c-2]O */ \
        float bq = __shfl_sync(0xffffffffu, p1E, sl);  /* A1[c-2]E */         \
        float e  = __shfl_sync(0xffffffffu, p2O, sl);  /* A2[c-1]E, [c-2]O */ \
        float f  = __shfl_sync(0xffffffffu, p2E, sl);  /* A2[c-2]E */         \
        float kO = __shfl_sync(0xffffffffu, CDO, sl);  /* C_D[c-1]E */        \
        float AD_E = CDE + fminf(fminf(p1E, a), e);                           \
        float AD_O = CDO + fminf(fminf(p1O, p1E), p2E);                       \
        float t1E  = CDE + fminf(p1E, e);                                     \
        float t1O  = CDO + fminf(p1O, p2E);                                   \
        float t3E  = kO  + fminf(bq, f);                                      \
        float t3O  = CDE + fminf(a, e);                                       \
        float AE_E = CEE + fminf(fminf(t1E, a),   t3E);                       \
        float AE_O = CEO + fminf(fminf(t1O, p1E), t3O);                       \
        if ((D) == 1022 && t == 31) out[b] = AD_O;  /* cell 63 = (511,511) */ \
        p2E = AD_E; p2O = AD_O; p1E = AE_E; p1O = AE_O;                       \
    }

    // prologue: D=2..14 (slots 1..7), then 63 x 8 rounds: D=16..1022
    PSTEP( 2, q1E0,q1O0,q1E1,q1O1)
    PSTEP( 4, q2E0,q2O0,q2E1,q2O1)
    PSTEP( 6, q3E0,q3O0,q3E1,q3O1)
    PSTEP( 8, q4E0,q4O0,q4E1,q4O1)
    PSTEP(10, q5E0,q5O0,q5E1,q5O1)
    PSTEP(12, q6E0,q6O0,q6E1,q6O1)
    PSTEP(14, q7E0,q7O0,q7E1,q7O1)
    for (int dbase = 16; dbase <= 1008; dbase += 16) {
        PSTEP(dbase +  0, q0E0,q0O0,q0E1,q0O1)
        PSTEP(dbase +  2, q1E0,q1O0,q1E1,q1O1)
        PSTEP(dbase +  4, q2E0,q2O0,q2E1,q2O1)
        PSTEP(dbase +  6, q3E0,q3O0,q3E1,q3O1)
        PSTEP(dbase +  8, q4E0,q4O0,q4E1,q4O1)
        PSTEP(dbase + 10, q5E0,q5O0,q5E1,q5O1)
        PSTEP(dbase + 12, q6E0,q6O0,q6E1,q6O1)
        PSTEP(dbase + 14, q7E0,q7O0,q7E1,q7O1)
    }
#undef PSTEP
#undef LOADSLOT
}

// ---------------------------------------------------------------------------
extern "C" void kernel_launch(void* const* d_in, const int* in_sizes, int n_in,
                              void* d_out, int out_size) {
    const float* x1 = (const float*)d_in[0];
    const float* x2 = (const float*)d_in[1];
    float* out = (float*)d_out;

    noop_kernel<<<1, 32>>>();                           // slot 0
    fill_kernel<<<4160, 256>>>();                       // slot 1
    norm_kernel<<<(2 * BB * TT) / 8, 256>>>(x1, x2);    // slot 2
    dim3 g(TT / TI, BB);
    cost_kernel<<<g, 128>>>();                          // slot 3 (profiled)
    dtw_kernel<<<BB, 32>>>(out);                        // slot 4
}